// round 5
// baseline (speedup 1.0000x reference)
#include <cuda_runtime.h>
#include <cstdint>

// ============================================================================
// OneHotEncoding via receiver-box candidate filtering (no index build).
//
// Output layout (float32):
//   [0, 4L)            input_tensor: per point (x, y, z, one_hot)
//   [4L, 4L+3B)        closest_points [B,3]
//   [4L+3B, 4L+4B)     min_index as float [B]
//
// K1 ub_kernel    : per receiver, exact min over first SAMPLES points; seeds
//                   g_best[r] with a VALID packed (d2<<32|idx) upper bound.
// K2 lists_kernel : 16^3 cell -> list of receivers whose [r-UB, r+UB]^3 box
//                   intersects the cell. Thread-per-cell, no atomics.
//                   Unconditionally correct: true NN lies within UB of r.
// K3 main_kernel  : stream pts once; write out[L,4]; for receivers listed in
//                   the point's cell, eval d2 + rare atomicMin packed u64.
//                   LAST-FINISHING BLOCK finalizes (closest_points, min_index,
//                   one-hot scatter + reference's index-0 quirk) — saves a
//                   whole launch (R4 lesson: tiny kernels cost ~5us each).
//
// No global-atomic hot spots (R3 lesson). All device state re-seeded or
// self-reset every call => graph-replay deterministic.
// ============================================================================

#define GC       16
#define CELLS    (GC * GC * GC)        // 4096
#define MAXB     128
#define SAMPLES  8192

__device__ unsigned long long g_best[MAXB];          // packed (d2bits<<32 | idx)
__device__ unsigned int       g_lcnt[CELLS];         // receivers per cell
__device__ unsigned char      g_list[CELLS * MAXB];  // receiver ids per cell
__device__ unsigned int       g_done;                // zero-init; self-resetting

__device__ __forceinline__ int cell_clamp(int c) {
    c = c < 0 ? 0 : c;
    return c > GC - 1 ? GC - 1 : c;
}
__device__ __forceinline__ int cell_of(float x) {
    return cell_clamp(__float2int_rd(x * (float)GC));
}

// ---------------------------------------------------------------------------
// K1: one block per receiver; exact brute-force min over first n sample points.
__global__ void __launch_bounds__(256)
ub_kernel(const float* __restrict__ pts, const float* __restrict__ recv, int L)
{
    const int b   = blockIdx.x;
    const int tid = threadIdx.x;
    const float rx = recv[3 * b + 0];
    const float ry = recv[3 * b + 1];
    const float rz = recv[3 * b + 2];

    const int n = (L < SAMPLES) ? L : SAMPLES;
    unsigned long long best = ~0ull;
    for (int p = tid; p < n; p += 256) {
        float dx = pts[3 * p + 0] - rx;
        float dy = pts[3 * p + 1] - ry;
        float dz = pts[3 * p + 2] - rz;
        float d2 = dx * dx + dy * dy + dz * dz;
        unsigned long long pk =
            (((unsigned long long)__float_as_uint(d2)) << 32) |
            (unsigned long long)(unsigned int)p;
        if (pk < best) best = pk;
    }
#pragma unroll
    for (int m = 16; m > 0; m >>= 1) {
        unsigned long long o = __shfl_xor_sync(0xffffffffu, best, m);
        if (o < best) best = o;
    }
    __shared__ unsigned long long s_b[8];
    if ((tid & 31) == 0) s_b[tid >> 5] = best;
    __syncthreads();
    if (tid == 0) {
        unsigned long long bb = s_b[0];
#pragma unroll
        for (int w = 1; w < 8; ++w) if (s_b[w] < bb) bb = s_b[w];
        g_best[b] = bb;                 // valid upper bound (actual point)
    }
}

// ---------------------------------------------------------------------------
// K2: thread-per-cell; build cell -> receiver candidate lists. No atomics.
__global__ void __launch_bounds__(512)
lists_kernel(const float* __restrict__ recv, int B)
{
    __shared__ int s_lx[MAXB], s_hx[MAXB], s_ly[MAXB], s_hy[MAXB],
                   s_lz[MAXB], s_hz[MAXB];
    const int tid = threadIdx.x;

    if (tid < B) {
        float ub2 = __uint_as_float((unsigned int)(g_best[tid] >> 32));
        float ub  = sqrtf(ub2) * 1.0001f + 1e-7f;   // ulp guard
        float rx = recv[3 * tid + 0];
        float ry = recv[3 * tid + 1];
        float rz = recv[3 * tid + 2];
        s_lx[tid] = cell_of(rx - ub);  s_hx[tid] = cell_of(rx + ub);
        s_ly[tid] = cell_of(ry - ub);  s_hy[tid] = cell_of(ry + ub);
        s_lz[tid] = cell_of(rz - ub);  s_hz[tid] = cell_of(rz + ub);
    }
    __syncthreads();

    const int cell = blockIdx.x * 512 + tid;        // 8 blocks x 512 = 4096
    if (cell >= CELLS) return;
    const int cx = cell & (GC - 1);
    const int cy = (cell >> 4) & (GC - 1);
    const int cz = cell >> 8;

    unsigned int n = 0;
    for (int r = 0; r < B; ++r) {
        bool hit = (cx >= s_lx[r]) & (cx <= s_hx[r]) &
                   (cy >= s_ly[r]) & (cy <= s_hy[r]) &
                   (cz >= s_lz[r]) & (cz <= s_hz[r]);
        if (hit) g_list[cell * MAXB + n++] = (unsigned char)r;
    }
    g_lcnt[cell] = n;
}

// ---------------------------------------------------------------------------
// K3: stream all points once; write out[L,4]; rare candidate evals + atomics.
//     Last-finishing block performs finalize (fused fin_kernel).
__global__ void __launch_bounds__(512)
main_kernel(const float* __restrict__ pts, const float* __restrict__ recv,
            float* __restrict__ out, int L, int B)
{
    __shared__ float srx[MAXB], sry[MAXB], srz[MAXB];
    const int tid = threadIdx.x;
    if (tid < B) {
        srx[tid] = recv[3 * tid + 0];
        sry[tid] = recv[3 * tid + 1];
        srz[tid] = recv[3 * tid + 2];
    }
    __syncthreads();

    const int nGrp   = (L + 3) >> 2;                 // groups of 4 points
    const int gid    = blockIdx.x * 512 + tid;
    const int stride = gridDim.x * 512;

    for (int g = gid; g < nGrp; g += stride) {
        const int p0 = 4 * g;
        float x[4], y[4], z[4];
        if (p0 + 3 < L) {                            // fast path: 3x float4
            const float4* src = reinterpret_cast<const float4*>(pts + 3 * p0);
            float4 a = src[0], bq = src[1], c = src[2];
            x[0]=a.x;  y[0]=a.y;  z[0]=a.z;
            x[1]=a.w;  y[1]=bq.x; z[1]=bq.y;
            x[2]=bq.z; y[2]=bq.w; z[2]=c.x;
            x[3]=c.y;  y[3]=c.z;  z[3]=c.w;
        } else {
#pragma unroll
            for (int j = 0; j < 4; ++j) {
                int p = p0 + j;
                x[j] = (p < L) ? pts[3 * p + 0] : 2.0f;   // 2.0 -> never listed
                y[j] = (p < L) ? pts[3 * p + 1] : 2.0f;
                z[j] = (p < L) ? pts[3 * p + 2] : 2.0f;
            }
        }

#pragma unroll
        for (int j = 0; j < 4; ++j) {
            const int p = p0 + j;
            if (p >= L) break;
            *reinterpret_cast<float4*>(out + 4 * (size_t)p) =
                make_float4(x[j], y[j], z[j], 0.0f);

            int c = (cell_of(z[j]) * GC + cell_of(y[j])) * GC + cell_of(x[j]);
            unsigned int n = g_lcnt[c];
            for (unsigned int k = 0; k < n; ++k) {
                int r = g_list[c * MAXB + k];
                float dx = x[j] - srx[r];
                float dy = y[j] - sry[r];
                float dz = z[j] - srz[r];
                float d2 = dx * dx + dy * dy + dz * dz;
                unsigned long long pk =
                    (((unsigned long long)__float_as_uint(d2)) << 32) |
                    (unsigned long long)(unsigned int)p;
                // stale-high read is safe: atomicMin is authoritative
                if (pk < g_best[r]) atomicMin(&g_best[r], pk);
            }
        }
    }

    // ---- fused finalize: last-finishing block ----
    __threadfence();
    __syncthreads();
    __shared__ bool is_last;
    if (tid == 0) is_last = (atomicAdd(&g_done, 1u) == gridDim.x - 1);
    __syncthreads();
    if (!is_last) return;

    if (tid < B) {
        // authoritative L1-bypassing read: atomicMin with max operand
        unsigned long long bb = atomicMin(&g_best[tid], ~0ull);
        unsigned int idx = (unsigned int)(bb & 0xffffffffull);
        float* cp = out + 4 * (size_t)L;
        cp[3 * tid + 0] = pts[3 * idx + 0];
        cp[3 * tid + 1] = pts[3 * idx + 1];
        cp[3 * tid + 2] = pts[3 * idx + 2];
        out[4 * (size_t)L + 3 * B + tid] = (float)idx;   // min_index as float
        out[4 * (size_t)idx + 3] = 1.0f;                 // one-hot scatter
    }
    if (tid == 0) {
        if (B > 1) out[3] = 1.0f;       // reference quirk: index 0 also set
        g_done = 0u;                    // reset for next graph replay
    }
}

// ---------------------------------------------------------------------------
extern "C" void kernel_launch(void* const* d_in, const int* in_sizes, int n_in,
                              void* d_out, int out_size)
{
    const float* pts  = (const float*)d_in[0];   // mesh_3D flattened [L,3]
    const float* recv = (const float*)d_in[1];   // receiver_pos [B,3]
    float* out = (float*)d_out;

    int L = in_sizes[0] / 3;   // 1,000,000
    int B = in_sizes[1] / 3;   // 128

    ub_kernel   <<<B, 256>>>(pts, recv, L);
    lists_kernel<<<(CELLS + 511) / 512, 512>>>(recv, B);
    main_kernel <<<152, 512>>>(pts, recv, out, L, B);
}